// round 13
// baseline (speedup 1.0000x reference)
#include <cuda_runtime.h>
#include <stdint.h>

#define D 128
#define C 10
#define WIN 384            // 2*D + edim
#define MAX_NODES 100000
#define PSTR 12            // P/Q row stride (48B)
#define SSTR 16            // staged-feature stride (floats), XOR-swizzled
#define RPB 256            // rows per tile
#define TILES 2            // tiles per edge block (seamless ring)

__device__ float g_P[MAX_NODES * PSTR];
__device__ float g_Q[MAX_NODES * PSTR];
__device__ int   g_is64;

__constant__ float cW[C * WIN];       // 15 KB: full weight matrix [C][384]

// ---- packed fp32 fma ---------------------------------------------------------
__device__ __forceinline__ void ffma2(unsigned long long& d,
                                      unsigned long long a,
                                      unsigned long long b) {
    asm("fma.rn.f32x2 %0, %1, %2, %0;" : "+l"(d) : "l"(a), "l"(b));
}
__device__ __forceinline__ float f2sum(unsigned long long v) {
    return __uint_as_float((unsigned)v) + __uint_as_float((unsigned)(v >> 32));
}

// ---- cp.async ----------------------------------------------------------------
__device__ __forceinline__ unsigned sptr(const void* p) {
    return (unsigned)__cvta_generic_to_shared(p);
}
__device__ __forceinline__ void cpa16(unsigned dst, const void* src) {
    asm volatile("cp.async.cg.shared.global [%0], [%1], 16;" :: "r"(dst), "l"(src));
}
__device__ __forceinline__ void cpa_commit() { asm volatile("cp.async.commit_group;"); }
__device__ __forceinline__ void cpa_wait1()  { asm volatile("cp.async.wait_group 1;"); }
__device__ __forceinline__ void cpa_wait0()  { asm volatile("cp.async.wait_group 0;"); }

// XOR-swizzled slot: row e, 16B-slot q  ->  conflict-free LDS.128 reads
__device__ __forceinline__ int sw_off(int e, int q) {
    return e * SSTR + ((q ^ ((e >> 1) & 3)) << 2);
}

// stage 64B chunk `ch` of rows [r0, r0+RPB) of a [*,128] fp32 matrix (block-wide)
template <int NT>
__device__ __forceinline__ void stage_chunk(float* dstbuf, const float* __restrict__ m,
                                            long r0, int ch, int t, long nmax) {
#pragma unroll
    for (int it = 0; it < RPB * 4 / NT; it++) {
        int idx = it * NT + t;
        int e = idx >> 2, q = idx & 3;
        long gr = r0 + e;
        if (gr > nmax) gr = nmax;
        cpa16(sptr(&dstbuf[sw_off(e, q)]), m + gr * D + ch * 16 + q * 4);
    }
}

// ---------------- stage 1: node projections, 3-buffer pipeline (R12 winner) --
__global__ void __launch_bounds__(256, 3)
node_kernel(const float* __restrict__ h,
            const float* __restrict__ b,
            int N,
            const unsigned long long* __restrict__ idx_probe) {
    __shared__ alignas(16) float sF[3][RPB * SSTR];   // 3 x 16 KB ring, static idx

    if (blockIdx.x == 0 && threadIdx.x == 0) {
        int ok = 1;
#pragma unroll
        for (int i = 0; i < 64; i++)
            if ((idx_probe[i] >> 32) != 0ULL) ok = 0;
        g_is64 = ok;
    }

    int t = threadIdx.x;
    long n0 = (long)blockIdx.x * RPB;

    stage_chunk<256>(sF[0], h, n0, 0, t, N - 1); cpa_commit();
    stage_chunk<256>(sF[1], h, n0, 1, t, N - 1); cpa_commit();

    unsigned long long acc[20];
#pragma unroll
    for (int c = 0; c < 20; c++) acc[c] = 0ULL;

#pragma unroll
    for (int ch = 0; ch < 8; ch++) {
        if (ch < 7) cpa_wait1(); else cpa_wait0();
        __syncthreads();
        if (ch + 2 < 8) {
            stage_chunk<256>(sF[(ch + 2) % 3], h, n0, ch + 2, t, N - 1);
            cpa_commit();
        }
        const float* buf = sF[ch % 3];
#pragma unroll
        for (int k4 = 0; k4 < 4; k4++) {
            ulonglong2 v = *(const ulonglong2*)&buf[sw_off(t, k4)];
            int kf = ch * 16 + k4 * 4;
#pragma unroll
            for (int c = 0; c < 10; c++) {
                ulonglong2 wu = *(const ulonglong2*)&cW[c * WIN + kf];      // Wu
                ulonglong2 wv = *(const ulonglong2*)&cW[c * WIN + D + kf];  // Wv
                ffma2(acc[c], v.x, wu.x);
                ffma2(acc[c], v.y, wu.y);
                ffma2(acc[10 + c], v.x, wv.x);
                ffma2(acc[10 + c], v.y, wv.y);
            }
        }
    }

    long n = n0 + t;
    if (n >= N) return;
    float r[10], s[10];
#pragma unroll
    for (int c = 0; c < 10; c++) {
        r[c] = f2sum(acc[c]) + __ldg(b + c);
        s[c] = f2sum(acc[10 + c]);
    }
    float4* Pp = (float4*)(g_P + n * PSTR);
    float4* Qp = (float4*)(g_Q + n * PSTR);
    Pp[0] = make_float4(r[0], r[1], r[2], r[3]);
    Pp[1] = make_float4(r[4], r[5], r[6], r[7]);
    Pp[2] = make_float4(r[8], r[9], 0.f, 0.f);
    Qp[0] = make_float4(s[0], s[1], s[2], s[3]);
    Qp[1] = make_float4(s[4], s[5], s[6], s[7]);
    Qp[2] = make_float4(s[8], s[9], 0.f, 0.f);
}

// ---------------- stage 2: per-edge, 2 tiles per block, seamless ring --------
__global__ void __launch_bounds__(128, 4)
edge_kernel(const float* __restrict__ eh,
            const void* __restrict__ src,
            const void* __restrict__ dst,
            float* __restrict__ out,
            int E) {
    __shared__ alignas(16) float sF[3][RPB * SSTR];   // 3 x 16 KB ring, static idx

    int t = threadIdx.x;
    long base = (long)blockIdx.x * (TILES * RPB);
    int is64 = g_is64;

    // stage global chunk g: tile g>>3, chunk g&7, slot g%3 (g compile-time)
    stage_chunk<128>(sF[0], eh, base, 0, t, E - 1); cpa_commit();
    stage_chunk<128>(sF[1], eh, base, 1, t, E - 1); cpa_commit();

    unsigned long long acc[2][C];

#pragma unroll
    for (int g = 0; g < 8 * TILES; g++) {
        const int ch = g & 7, tt = g >> 3;
        const long e0 = base + (long)tt * RPB;

        if (ch == 0) {
#pragma unroll
            for (int j = 0; j < 2; j++)
#pragma unroll
                for (int c = 0; c < C; c++) acc[j][c] = 0ULL;
        }

        if (g < 8 * TILES - 1) cpa_wait1(); else cpa_wait0();   // stage(g) done
        __syncthreads();                                        // readers of g-1 done
        if (g + 2 < 8 * TILES) {                                // refill slot (g-1)%3
            stage_chunk<128>(sF[(g + 2) % 3],
                             eh, base + (long)((g + 2) >> 3) * RPB,
                             (g + 2) & 7, t, E - 1);
            cpa_commit();
        }

        const float* buf = sF[g % 3];
#pragma unroll
        for (int k4 = 0; k4 < 4; k4++) {
            ulonglong2 va = *(const ulonglong2*)&buf[sw_off(t, k4)];
            ulonglong2 vb = *(const ulonglong2*)&buf[sw_off(t + 128, k4)];
            int kf = ch * 16 + k4 * 4;
#pragma unroll
            for (int c = 0; c < C; c++) {
                ulonglong2 w = *(const ulonglong2*)&cW[c * WIN + 2 * D + kf];  // We
                ffma2(acc[0][c], va.x, w.x);
                ffma2(acc[0][c], va.y, w.y);
                ffma2(acc[1][c], vb.x, w.x);
                ffma2(acc[1][c], vb.y, w.y);
            }
        }

        if (ch == 7) {
            // tile tail — runs while next tile's staging is in flight
#pragma unroll
            for (int j = 0; j < 2; j++) {
                long e = e0 + t + j * 128;
                if (e >= E) continue;
                long s, d;
                if (is64) {
                    s = (long)((const long long*)src)[e];
                    d = (long)((const long long*)dst)[e];
                } else {
                    s = ((const int*)src)[e];
                    d = ((const int*)dst)[e];
                }
                float r[10];
#pragma unroll
                for (int c = 0; c < C; c++) r[c] = f2sum(acc[j][c]);

                const float4* Pp = (const float4*)(g_P + s * PSTR);
                const float4* Qp = (const float4*)(g_Q + d * PSTR);
                float4 pa = Pp[0], pb = Pp[1], pc = Pp[2];
                float4 qa = Qp[0], qb = Qp[1], qc = Qp[2];
                r[0] += pa.x + qa.x; r[1] += pa.y + qa.y;
                r[2] += pa.z + qa.z; r[3] += pa.w + qa.w;
                r[4] += pb.x + qb.x; r[5] += pb.y + qb.y;
                r[6] += pb.z + qb.z; r[7] += pb.w + qb.w;
                r[8] += pc.x + qc.x; r[9] += pc.y + qc.y;

                float2* op = (float2*)(out + e * C);
#pragma unroll
                for (int i = 0; i < 5; i++)
                    op[i] = make_float2(r[2 * i], r[2 * i + 1]);
            }
        }
    }
}

extern "C" void kernel_launch(void* const* d_in, const int* in_sizes, int n_in,
                              void* d_out, int out_size) {
    const float* h   = (const float*)d_in[0];
    const float* eh  = (const float*)d_in[1];
    const float* Ww  = (const float*)d_in[2];
    const float* Wb  = (const float*)d_in[3];
    const void*  src = d_in[4];
    const void*  dst = d_in[5];

    int N = in_sizes[0] / D;   // 100000
    int E = in_sizes[1] / D;   // 600000

    // ONE D2D copy of the full weight matrix into constant memory
    cudaMemcpyToSymbolAsync(cW, Ww, C * WIN * sizeof(float), 0,
                            cudaMemcpyDeviceToDevice, 0);

    node_kernel<<<(N + RPB - 1) / RPB, 256>>>(h, Wb, N,
                                              (const unsigned long long*)src);
    edge_kernel<<<(E + TILES * RPB - 1) / (TILES * RPB), 128>>>(
        eh, src, dst, (float*)d_out, E);
}

// round 14
// speedup vs baseline: 1.0468x; 1.0468x over previous
#include <cuda_runtime.h>
#include <stdint.h>

#define D 128
#define C 10
#define WIN 384            // 2*D + edim
#define MAX_NODES 100000
#define PSTR 12            // P/Q row stride (48B)
#define SSTR 16            // staged-feature stride (floats), XOR-swizzled
#define RPB 256            // rows per tile (both kernels)

__device__ float g_P[MAX_NODES * PSTR];
__device__ float g_Q[MAX_NODES * PSTR];
__device__ int   g_is64;

__constant__ float cW[C * WIN];       // 15 KB: full weight matrix [C][384]

// ---- packed fp32 fma ---------------------------------------------------------
__device__ __forceinline__ void ffma2(unsigned long long& d,
                                      unsigned long long a,
                                      unsigned long long b) {
    asm("fma.rn.f32x2 %0, %1, %2, %0;" : "+l"(d) : "l"(a), "l"(b));
}
__device__ __forceinline__ float f2sum(unsigned long long v) {
    return __uint_as_float((unsigned)v) + __uint_as_float((unsigned)(v >> 32));
}

// ---- cp.async ----------------------------------------------------------------
__device__ __forceinline__ unsigned sptr(const void* p) {
    return (unsigned)__cvta_generic_to_shared(p);
}
__device__ __forceinline__ void cpa16(unsigned dst, const void* src) {
    asm volatile("cp.async.cg.shared.global [%0], [%1], 16;" :: "r"(dst), "l"(src));
}
__device__ __forceinline__ void cpa_commit() { asm volatile("cp.async.commit_group;"); }
__device__ __forceinline__ void cpa_wait1()  { asm volatile("cp.async.wait_group 1;"); }
__device__ __forceinline__ void cpa_wait0()  { asm volatile("cp.async.wait_group 0;"); }

// XOR-swizzled slot: row e, 16B-slot q  ->  conflict-free LDS.128 reads
__device__ __forceinline__ int sw_off(int e, int q) {
    return e * SSTR + ((q ^ ((e >> 1) & 3)) << 2);
}

// stage 64B chunk `ch` of rows [r0, r0+RPB) of a [*,128] fp32 matrix (block-wide)
template <int NT>
__device__ __forceinline__ void stage_chunk(float* dstbuf, const float* __restrict__ m,
                                            long r0, int ch, int t, long nmax) {
#pragma unroll
    for (int it = 0; it < RPB * 4 / NT; it++) {
        int idx = it * NT + t;
        int e = idx >> 2, q = idx & 3;
        long gr = r0 + e;
        if (gr > nmax) gr = nmax;
        cpa16(sptr(&dstbuf[sw_off(e, q)]), m + gr * D + ch * 16 + q * 4);
    }
}

// ---------------- stage 1: node projections, 3-buffer pipeline (R12 winner) --
__global__ void __launch_bounds__(256, 3)
node_kernel(const float* __restrict__ h,
            const float* __restrict__ b,
            int N,
            const unsigned long long* __restrict__ idx_probe) {
    __shared__ alignas(16) float sF[3][RPB * SSTR];   // 3 x 16 KB ring, static idx

    if (blockIdx.x == 0 && threadIdx.x == 0) {
        int ok = 1;
#pragma unroll
        for (int i = 0; i < 64; i++)
            if ((idx_probe[i] >> 32) != 0ULL) ok = 0;
        g_is64 = ok;
    }

    int t = threadIdx.x;
    long n0 = (long)blockIdx.x * RPB;

    stage_chunk<256>(sF[0], h, n0, 0, t, N - 1); cpa_commit();
    stage_chunk<256>(sF[1], h, n0, 1, t, N - 1); cpa_commit();

    unsigned long long acc[20];
#pragma unroll
    for (int c = 0; c < 20; c++) acc[c] = 0ULL;

#pragma unroll
    for (int ch = 0; ch < 8; ch++) {
        if (ch < 7) cpa_wait1(); else cpa_wait0();
        __syncthreads();
        if (ch + 2 < 8) {
            stage_chunk<256>(sF[(ch + 2) % 3], h, n0, ch + 2, t, N - 1);
            cpa_commit();
        }
        const float* buf = sF[ch % 3];
#pragma unroll
        for (int k4 = 0; k4 < 4; k4++) {
            ulonglong2 v = *(const ulonglong2*)&buf[sw_off(t, k4)];
            int kf = ch * 16 + k4 * 4;
#pragma unroll
            for (int c = 0; c < 10; c++) {
                ulonglong2 wu = *(const ulonglong2*)&cW[c * WIN + kf];      // Wu
                ulonglong2 wv = *(const ulonglong2*)&cW[c * WIN + D + kf];  // Wv
                ffma2(acc[c], v.x, wu.x);
                ffma2(acc[c], v.y, wu.y);
                ffma2(acc[10 + c], v.x, wv.x);
                ffma2(acc[10 + c], v.y, wv.y);
            }
        }
    }

    long n = n0 + t;
    if (n >= N) return;
    float r[10], s[10];
#pragma unroll
    for (int c = 0; c < 10; c++) {
        r[c] = f2sum(acc[c]) + __ldg(b + c);
        s[c] = f2sum(acc[10 + c]);
    }
    float4* Pp = (float4*)(g_P + n * PSTR);
    float4* Qp = (float4*)(g_Q + n * PSTR);
    Pp[0] = make_float4(r[0], r[1], r[2], r[3]);
    Pp[1] = make_float4(r[4], r[5], r[6], r[7]);
    Pp[2] = make_float4(r[8], r[9], 0.f, 0.f);
    Qp[0] = make_float4(s[0], s[1], s[2], s[3]);
    Qp[1] = make_float4(s[4], s[5], s[6], s[7]);
    Qp[2] = make_float4(s[8], s[9], 0.f, 0.f);
}

// ---------------- stage 2: per-edge, 3-buffer pipeline, G=1 @ 256 thr --------
__global__ void __launch_bounds__(256, 4)
edge_kernel(const float* __restrict__ eh,
            const void* __restrict__ src,
            const void* __restrict__ dst,
            float* __restrict__ out,
            int E) {
    __shared__ alignas(16) float sF[3][RPB * SSTR];   // 3 x 16 KB ring, static idx

    int t = threadIdx.x;
    long e0 = (long)blockIdx.x * RPB;
    int is64 = g_is64;                 // hoisted

    stage_chunk<256>(sF[0], eh, e0, 0, t, E - 1); cpa_commit();
    stage_chunk<256>(sF[1], eh, e0, 1, t, E - 1); cpa_commit();

    unsigned long long acc[C];
#pragma unroll
    for (int c = 0; c < C; c++) acc[c] = 0ULL;

#pragma unroll
    for (int ch = 0; ch < 8; ch++) {
        if (ch < 7) cpa_wait1(); else cpa_wait0();
        __syncthreads();
        if (ch + 2 < 8) {
            stage_chunk<256>(sF[(ch + 2) % 3], eh, e0, ch + 2, t, E - 1);
            cpa_commit();
        }
        const float* buf = sF[ch % 3];
#pragma unroll
        for (int k4 = 0; k4 < 4; k4++) {
            ulonglong2 v = *(const ulonglong2*)&buf[sw_off(t, k4)];
            int kf = ch * 16 + k4 * 4;
#pragma unroll
            for (int c = 0; c < C; c++) {
                ulonglong2 w = *(const ulonglong2*)&cW[c * WIN + 2 * D + kf];  // We
                ffma2(acc[c], v.x, w.x);
                ffma2(acc[c], v.y, w.y);
            }
        }
    }

    long e = e0 + t;
    if (e >= E) return;
    long s, d;
    if (is64) {
        s = (long)((const long long*)src)[e];
        d = (long)((const long long*)dst)[e];
    } else {
        s = ((const int*)src)[e];
        d = ((const int*)dst)[e];
    }
    float r[10];
#pragma unroll
    for (int c = 0; c < C; c++) r[c] = f2sum(acc[c]);

    const float4* Pp = (const float4*)(g_P + s * PSTR);
    const float4* Qp = (const float4*)(g_Q + d * PSTR);
    float4 pa = Pp[0], pb = Pp[1], pc = Pp[2];
    float4 qa = Qp[0], qb = Qp[1], qc = Qp[2];
    r[0] += pa.x + qa.x; r[1] += pa.y + qa.y; r[2] += pa.z + qa.z; r[3] += pa.w + qa.w;
    r[4] += pb.x + qb.x; r[5] += pb.y + qb.y; r[6] += pb.z + qb.z; r[7] += pb.w + qb.w;
    r[8] += pc.x + qc.x; r[9] += pc.y + qc.y;

    float2* op = (float2*)(out + e * C);
#pragma unroll
    for (int i = 0; i < 5; i++)
        op[i] = make_float2(r[2 * i], r[2 * i + 1]);
}

extern "C" void kernel_launch(void* const* d_in, const int* in_sizes, int n_in,
                              void* d_out, int out_size) {
    const float* h   = (const float*)d_in[0];
    const float* eh  = (const float*)d_in[1];
    const float* Ww  = (const float*)d_in[2];
    const float* Wb  = (const float*)d_in[3];
    const void*  src = d_in[4];
    const void*  dst = d_in[5];

    int N = in_sizes[0] / D;   // 100000
    int E = in_sizes[1] / D;   // 600000

    // ONE D2D copy of the full weight matrix into constant memory
    cudaMemcpyToSymbolAsync(cW, Ww, C * WIN * sizeof(float), 0,
                            cudaMemcpyDeviceToDevice, 0);

    node_kernel<<<(N + RPB - 1) / RPB, 256>>>(h, Wb, N,
                                              (const unsigned long long*)src);
    edge_kernel<<<(E + RPB - 1) / RPB, 256>>>(eh, src, dst, (float*)d_out, E);
}